// round 9
// baseline (speedup 1.0000x reference)
#include <cuda_runtime.h>
#include <cuda_bf16.h>
#include <cstdint>

#define B_   4096
#define T_   128
#define H_   128
#define G_   512
#define M_   32     // batch rows per CTA (MMA N)
#define NTHR 256    // 8 warps; warp w owns cells [w*16, w*16+16) x all 4 gates

// ---------------- device scratch ----------------
// Packed W images (K=128 each, 4 chunks x 64KB; chunk = [hi 32KB | lo 32KB], ldmatrix-swizzled):
// slots 0..2 = W_hh layers 0..2 ; slots 3..4 = W_ih layers 1..2
__device__ __align__(1024) unsigned char g_wtA[5][4 * 65536];
__device__ float g_bias[3][G_];
__device__ float g_buf[(size_t)B_ * T_ * H_];   // fp32 activations (layer outputs)
__device__ float g_gx[(size_t)B_ * T_ * G_];    // fragment-ordered gate pre-activations (1 GB)

// ---------------- helpers ----------------
__device__ __forceinline__ float tanha(float x) {
    float r; asm("tanh.approx.f32 %0, %1;" : "=f"(r) : "f"(x)); return r;
}
__device__ __forceinline__ float sigm(float x) { return 0.5f * tanha(0.5f * x) + 0.5f; }

union BU { __nv_bfloat162 h; uint32_t u; };
__device__ __forceinline__ uint32_t pack2(float a, float b) {
    BU v; v.h = __floats2bfloat162_rn(a, b); return v.u;
}
__device__ __forceinline__ float resid(float a) {
    return a - __bfloat162float(__float2bfloat16_rn(a));
}

#define HMMA(d, a, b) asm volatile( \
    "mma.sync.aligned.m16n8k16.row.col.f32.bf16.bf16.f32 " \
    "{%0,%1,%2,%3}, {%4,%5,%6,%7}, {%8,%9}, {%0,%1,%2,%3};" \
    : "+f"((d)[0]), "+f"((d)[1]), "+f"((d)[2]), "+f"((d)[3]) \
    : "r"((a)[0]), "r"((a)[1]), "r"((a)[2]), "r"((a)[3]), "r"((b)[0]), "r"((b)[1]))

#define LDSM4(r, addr) asm volatile( \
    "ldmatrix.sync.aligned.m8n8.x4.shared.b16 {%0,%1,%2,%3}, [%4];" \
    : "=r"((r)[0]), "=r"((r)[1]), "=r"((r)[2]), "=r"((r)[3]) : "r"(addr))

#define LDS32(r, addr) asm volatile("ld.shared.b32 %0, [%1];" : "=r"(r) : "r"(addr))

__device__ __forceinline__ void mbar_init(uint32_t a, uint32_t cnt) {
    asm volatile("mbarrier.init.shared.b64 [%0], %1;" :: "r"(a), "r"(cnt) : "memory");
}
__device__ __forceinline__ void mbar_expect(uint32_t a, uint32_t bytes) {
    asm volatile("mbarrier.arrive.expect_tx.shared::cta.b64 _, [%0], %1;"
                 :: "r"(a), "r"(bytes) : "memory");
}
__device__ __forceinline__ void mbar_wait(uint32_t a, uint32_t parity) {
    asm volatile(
        "{\n\t.reg .pred P;\n"
        "WL%=:\n\tmbarrier.try_wait.parity.shared::cta.b64 P, [%0], %1;\n"
        "\t@!P bra WL%=;\n\t}"
        :: "r"(a), "r"(parity) : "memory");
}
__device__ __forceinline__ void bulk_cp(uint32_t dst, const void* src, uint32_t bytes, uint32_t mbar) {
    asm volatile("cp.async.bulk.shared::cluster.global.mbarrier::complete_tx::bytes "
                 "[%0], [%1], %2, [%3];"
                 :: "r"(dst), "l"(src), "r"(bytes), "r"(mbar) : "memory");
}

// One K=32 chunk of 3-term MMA. SROW = u row stride in bytes.
__device__ __forceinline__ void mma_chunk(uint32_t Ah, uint32_t U0, uint32_t U1,
                                          int c, int wid, int lane,
                                          float acc[4][4][4]) {
    const int g = lane >> 2, t4 = lane & 3;
    const uint32_t Al = Ah + 32768;
    #pragma unroll
    for (int ks = 0; ks < 2; ks++) {
        const int kb = c * 32 + ks * 16;
        uint32_t bh[4][2], bl[4][2];
        #pragma unroll
        for (int nt = 0; nt < 4; nt++) {
            uint32_t uoff = (uint32_t)(nt * 8 + g) * 272 + (kb + 2 * t4) * 2;
            LDS32(bh[nt][0], U0 + uoff); LDS32(bh[nt][1], U0 + uoff + 16);
            LDS32(bl[nt][0], U1 + uoff); LDS32(bl[nt][1], U1 + uoff + 16);
        }
        unsigned p0  = (unsigned)wid * 64 + (lane & 15);
        unsigned seg = ((unsigned)(ks * 2 + (lane >> 4))) ^ ((p0 >> 1) & 3);
        uint32_t ab  = p0 * 64 + seg * 16;
        #pragma unroll
        for (int m = 0; m < 4; m++) {
            uint32_t ah[4], al[4];
            LDSM4(ah, Ah + ab + m * 1024);
            LDSM4(al, Al + ab + m * 1024);
            #pragma unroll
            for (int nt = 0; nt < 4; nt++) {
                HMMA(acc[m][nt], ah, bh[nt]);   // Whi*Uhi
                HMMA(acc[m][nt], ah, bl[nt]);   // Whi*Ulo
                HMMA(acc[m][nt], al, bh[nt]);   // Wlo*Uhi
            }
        }
    }
}

// ---------------- prep: pack a K=128 weight into the ldmatrix image (bf16 hi/lo) ----------------
__global__ void prep_w(const float* __restrict__ wih, const float* __restrict__ whh,
                       int slot, int IN) {
    int k = blockIdx.x;           // 0..127
    int row = threadIdx.x;        // 0..511 = gate*128 + cell
    float v = (k < IN) ? wih[row * IN + k] : whh[row * H_ + k];
    __nv_bfloat16 hi = __float2bfloat16_rn(v);
    __nv_bfloat16 lo = __float2bfloat16_rn(v - __bfloat162float(hi));
    int gate = row >> 7, cell = row & 127;
    unsigned p = ((cell >> 4) << 6) + (gate << 4) + (cell & 15);
    int chunk = k >> 5;
    unsigned kb = (unsigned)(k & 31) * 2;
    unsigned off = p * 64 + ((((kb >> 4) ^ ((p >> 1) & 3)) << 4) | (kb & 15));
    *(__nv_bfloat16*)&g_wtA[slot][chunk * 65536 + off]         = hi;
    *(__nv_bfloat16*)&g_wtA[slot][chunk * 65536 + 32768 + off] = lo;
}

__global__ void prep_bias(const float* __restrict__ bih, const float* __restrict__ bhh, int layer) {
    int c = threadIdx.x;
    g_bias[layer][c] = bih[c] + bhh[c];
}

// ---------------- gx for layer 0 (IN=8): plain FFMA, fragment-ordered output ----------------
__global__ void gx0_kernel(const float* __restrict__ x, const float* __restrict__ wih0) {
    __shared__ float ws[512 * 8];
    __shared__ float xs[32 * 8];
    int bt = blockIdx.x, t = blockIdx.y;
    int tid = threadIdx.x;
    for (int i = tid; i < 4096; i += NTHR) ws[i] = wih0[i];
    for (int i = tid; i < 256; i += NTHR) {
        int r = i >> 3, k = i & 7;
        xs[i] = x[((size_t)(bt * 32 + r) * T_ + t) * 8 + k];
    }
    __syncthreads();
    int wid = tid >> 5, lane = tid & 31, g = lane >> 2, t4 = lane & 3;
    int cell0 = wid * 16 + g;
    size_t base = ((size_t)bt * T_ + t) * 16384;
    #pragma unroll
    for (int m = 0; m < 4; m++)
        #pragma unroll
        for (int nt = 0; nt < 4; nt++) {
            float4 o;
            float* op = &o.x;
            #pragma unroll
            for (int e = 0; e < 4; e++) {
                int cell = cell0 + (e >> 1) * 8;
                int r = nt * 8 + t4 * 2 + (e & 1);
                float a = g_bias[0][m * 128 + cell];
                const float* wr = &ws[(m * 128 + cell) * 8];
                const float* xr = &xs[r * 8];
                #pragma unroll
                for (int k = 0; k < 8; k++) a = fmaf(wr[k], xr[k], a);
                op[e] = a;
            }
            *(float4*)&g_gx[base + (size_t)(m * 4 + nt) * 1024 + tid * 4] = o;
        }
}

// ---------------- phase A: gx = prev_h @ W_ih^T + bias (layers 1,2), K=128 ----------------
__global__ void __launch_bounds__(NTHR, 1)
gx_gemm(int wslot, int layer) {
    extern __shared__ unsigned char smem[];
    uint32_t sb = (uint32_t)__cvta_generic_to_shared(smem);
    uint32_t s0 = (sb + 1023) & ~1023u;
    uint32_t MB = s0;
    uint32_t A0 = s0 + 128;
    uint32_t U0 = A0 + 131072;
    uint32_t U1 = U0 + 32 * 272;
    unsigned char* sp = smem + (s0 - sb);
    const unsigned UH = 128 + 131072, UL = UH + 32 * 272;

    const int tid = threadIdx.x, wid = tid >> 5, lane = tid & 31;
    const int g = lane >> 2;
    const int bt = blockIdx.x, b0 = bt * M_, ts = blockIdx.y;

    if (tid == 0) { mbar_init(MB, 1); mbar_init(MB + 8, 1); }
    __syncthreads();
    if (tid == 0) { mbar_expect(MB, 65536); bulk_cp(A0, g_wtA[wslot], 65536, MB); }

    const int cell0 = wid * 16 + g;
    float bias_v[4][2];
    #pragma unroll
    for (int m = 0; m < 4; m++) {
        bias_v[m][0] = g_bias[layer][m * 128 + cell0];
        bias_v[m][1] = g_bias[layer][m * 128 + cell0 + 8];
    }
    float acc[4][4][4];
    #pragma unroll
    for (int m = 0; m < 4; m++)
        #pragma unroll
        for (int nt = 0; nt < 4; nt++) {
            acc[m][nt][0] = acc[m][nt][1] = bias_v[m][0];
            acc[m][nt][2] = acc[m][nt][3] = bias_v[m][1];
        }

    int ph0 = 0, ph1 = 0, gc = 0;

    for (int tt = 0; tt < 8; tt++) {
        int t = ts * 8 + tt;
        // stage x_t (prev layer h, 128 floats/row) as bf16 hi/lo
        for (int i = tid; i < 32 * 32; i += NTHR) {
            int r = i >> 5, kv = i & 31;
            float4 v = *(const float4*)&g_buf[((size_t)(b0 + r) * T_ + t) * H_ + kv * 4];
            unsigned off = (unsigned)r * 272 + kv * 8;
            *(uint32_t*)(sp + UH + off)     = pack2(v.x, v.y);
            *(uint32_t*)(sp + UH + off + 4) = pack2(v.z, v.w);
            *(uint32_t*)(sp + UL + off)     = pack2(resid(v.x), resid(v.y));
            *(uint32_t*)(sp + UL + off + 4) = pack2(resid(v.z), resid(v.w));
        }
        for (int c = 0; c < 4; c++) {
            __syncthreads();
            int cur = gc & 1;
            if (tid == 0 && !(tt == 7 && c == 3)) {
                int cn = (c + 1) & 3;
                mbar_expect(MB + (cur ^ 1) * 8, 65536);
                bulk_cp(A0 + (cur ^ 1) * 65536, g_wtA[wslot] + (size_t)cn * 65536,
                        65536, MB + (cur ^ 1) * 8);
            }
            if (cur == 0) { mbar_wait(MB, ph0);     ph0 ^= 1; }
            else          { mbar_wait(MB + 8, ph1); ph1 ^= 1; }
            mma_chunk(A0 + (unsigned)cur * 65536, U0, U1, c, wid, lane, acc);
            gc++;
        }
        __syncthreads();
        // store fragment-ordered gx, reset acc to bias
        size_t base = ((size_t)bt * T_ + t) * 16384;
        #pragma unroll
        for (int m = 0; m < 4; m++)
            #pragma unroll
            for (int nt = 0; nt < 4; nt++) {
                float4 o = make_float4(acc[m][nt][0], acc[m][nt][1],
                                       acc[m][nt][2], acc[m][nt][3]);
                *(float4*)&g_gx[base + (size_t)(m * 4 + nt) * 1024 + tid * 4] = o;
                acc[m][nt][0] = acc[m][nt][1] = bias_v[m][0];
                acc[m][nt][2] = acc[m][nt][3] = bias_v[m][1];
            }
    }
}

// ---------------- phase B: recurrence, K=128 (W_hh only), acc seeded from g_gx ----------------
__global__ void __launch_bounds__(NTHR, 1)
lstm_rec(int wslot) {
    extern __shared__ unsigned char smem[];
    uint32_t sb = (uint32_t)__cvta_generic_to_shared(smem);
    uint32_t s0 = (sb + 1023) & ~1023u;
    uint32_t MB = s0;
    uint32_t A0 = s0 + 128;
    uint32_t U0 = A0 + 131072;
    uint32_t U1 = U0 + 32 * 272;
    unsigned char* sp = smem + (s0 - sb);
    const unsigned UH = 128 + 131072, UL = UH + 32 * 272;

    const int tid = threadIdx.x, wid = tid >> 5, lane = tid & 31;
    const int g = lane >> 2, t4 = lane & 3;
    const int bt = blockIdx.x, b0 = bt * M_;

    // zero u (h0 = 0)
    for (int i = tid; i < (64 * 272) / 4; i += NTHR) ((uint32_t*)(sp + UH))[i] = 0;

    if (tid == 0) { mbar_init(MB, 1); mbar_init(MB + 8, 1); }
    __syncthreads();
    if (tid == 0) { mbar_expect(MB, 65536); bulk_cp(A0, g_wtA[wslot], 65536, MB); }

    const int cell0 = wid * 16 + g;
    float acc[4][4][4];
    float cst[16];
    #pragma unroll
    for (int i = 0; i < 16; i++) cst[i] = 0.f;

    int ph0 = 0, ph1 = 0, gc = 0;

    for (int t = 0; t < T_; t++) {
        // seed acc with gx (bias included), coalesced LDG.128
        size_t base = ((size_t)bt * T_ + t) * 16384;
        #pragma unroll
        for (int m = 0; m < 4; m++)
            #pragma unroll
            for (int nt = 0; nt < 4; nt++) {
                float4 v = *(const float4*)&g_gx[base + (size_t)(m * 4 + nt) * 1024 + tid * 4];
                acc[m][nt][0] = v.x; acc[m][nt][1] = v.y;
                acc[m][nt][2] = v.z; acc[m][nt][3] = v.w;
            }
        for (int c = 0; c < 4; c++) {
            __syncthreads();   // u writes of t-1 done; W buffer reads of gc-2 done
            int cur = gc & 1;
            if (tid == 0 && !(t == T_ - 1 && c == 3)) {
                int cn = (c + 1) & 3;
                mbar_expect(MB + (cur ^ 1) * 8, 65536);
                bulk_cp(A0 + (cur ^ 1) * 65536, g_wtA[wslot] + (size_t)cn * 65536,
                        65536, MB + (cur ^ 1) * 8);
            }
            if (cur == 0) { mbar_wait(MB, ph0);     ph0 ^= 1; }
            else          { mbar_wait(MB + 8, ph1); ph1 ^= 1; }
            mma_chunk(A0 + (unsigned)cur * 65536, U0, U1, c, wid, lane, acc);
            gc++;
        }
        __syncthreads();   // all MMA reads of u done before h writes

        // epilogue: gates in registers, state update, write h (global fp32 + smem bf16 hi/lo)
        #pragma unroll
        for (int ci = 0; ci < 2; ci++)
            #pragma unroll
            for (int nt = 0; nt < 4; nt++)
                #pragma unroll
                for (int par = 0; par < 2; par++) {
                    int e = ci * 2 + par;
                    float vi = acc[0][nt][e], vf = acc[1][nt][e];
                    float vg = acc[2][nt][e], vo = acc[3][nt][e];
                    int sidx = ci * 8 + nt * 2 + par;
                    float cn = sigm(vf) * cst[sidx] + sigm(vi) * tanha(vg);
                    cst[sidx] = cn;
                    float h = sigm(vo) * tanha(cn);
                    int cell = cell0 + ci * 8;
                    int b    = nt * 8 + t4 * 2 + par;
                    g_buf[((size_t)(b0 + b) * T_ + t) * H_ + cell] = h;
                    __nv_bfloat16 hh = __float2bfloat16_rn(h);
                    __nv_bfloat16 hl = __float2bfloat16_rn(h - __bfloat162float(hh));
                    unsigned ho = (unsigned)b * 272 + cell * 2;
                    *(__nv_bfloat16*)(sp + UH + ho) = hh;
                    *(__nv_bfloat16*)(sp + UL + ho) = hl;
                }
    }
}

// ---------------- FC head ----------------
__global__ void fc_kernel(const float* __restrict__ w1, const float* __restrict__ b1,
                          const float* __restrict__ w2, const float* __restrict__ b2,
                          float* __restrict__ out) {
    __shared__ float hsh[H_];
    __shared__ float red[4];
    int b = blockIdx.x;
    int tid = threadIdx.x;  // 128 threads

    hsh[tid] = g_buf[((size_t)b * T_ + (T_ - 1)) * H_ + tid];
    __syncthreads();

    float partial = 0.f;
    if (tid < 64) {
        float d = b1[tid];
        const float* wr = w1 + tid * H_;
        #pragma unroll 8
        for (int k = 0; k < H_; k++) d += wr[k] * hsh[k];
        partial = fmaxf(d, 0.f) * w2[tid];
    }
    #pragma unroll
    for (int off = 16; off > 0; off >>= 1)
        partial += __shfl_down_sync(0xffffffff, partial, off);
    if ((tid & 31) == 0) red[tid >> 5] = partial;
    __syncthreads();
    if (tid == 0) out[b] = red[0] + red[1] + b2[0];
}

// ---------------- launch ----------------
extern "C" void kernel_launch(void* const* d_in, const int* in_sizes, int n_in,
                              void* d_out, int out_size) {
    const float* x     = (const float*)d_in[0];
    const float* wih0  = (const float*)d_in[1];
    const float* whh0  = (const float*)d_in[2];
    const float* bih0  = (const float*)d_in[3];
    const float* bhh0  = (const float*)d_in[4];
    const float* wih1  = (const float*)d_in[5];
    const float* whh1  = (const float*)d_in[6];
    const float* bih1  = (const float*)d_in[7];
    const float* bhh1  = (const float*)d_in[8];
    const float* wih2  = (const float*)d_in[9];
    const float* whh2  = (const float*)d_in[10];
    const float* bih2  = (const float*)d_in[11];
    const float* bhh2  = (const float*)d_in[12];
    const float* fc1w  = (const float*)d_in[13];
    const float* fc1b  = (const float*)d_in[14];
    const float* fc2w  = (const float*)d_in[15];
    const float* fc2b  = (const float*)d_in[16];

    const int SM = 1024 + 128 + 131072 + 64 * 272;   // 149,632 dyn smem
    cudaFuncSetAttribute(gx_gemm,  cudaFuncAttributeMaxDynamicSharedMemorySize, SM);
    cudaFuncSetAttribute(lstm_rec, cudaFuncAttributeMaxDynamicSharedMemorySize, SM);

    prep_w<<<128, 512>>>(nullptr, whh0, 0, 0);
    prep_w<<<128, 512>>>(nullptr, whh1, 1, 0);
    prep_w<<<128, 512>>>(nullptr, whh2, 2, 0);
    prep_w<<<128, 512>>>(wih1, nullptr, 3, 128);
    prep_w<<<128, 512>>>(wih2, nullptr, 4, 128);
    prep_bias<<<1, 512>>>(bih0, bhh0, 0);
    prep_bias<<<1, 512>>>(bih1, bhh1, 1);
    prep_bias<<<1, 512>>>(bih2, bhh2, 2);

    gx0_kernel<<<dim3(128, 128), NTHR>>>(x, wih0);        // layer 0 gx (FFMA)
    lstm_rec<<<128, NTHR, SM>>>(0);                       // layer 0 recurrence -> g_buf

    gx_gemm<<<dim3(128, 16), NTHR, SM>>>(3, 1);           // layer 1 gx (MMA)
    lstm_rec<<<128, NTHR, SM>>>(1);                       // layer 1 recurrence

    gx_gemm<<<dim3(128, 16), NTHR, SM>>>(4, 2);           // layer 2 gx
    lstm_rec<<<128, NTHR, SM>>>(2);                       // layer 2 recurrence

    fc_kernel<<<B_, 128>>>(fc1w, fc1b, fc2w, fc2b, (float*)d_out);
}

// round 10
// speedup vs baseline: 1.1465x; 1.1465x over previous
#include <cuda_runtime.h>
#include <cuda_bf16.h>
#include <cstdint>

#define B_   4096
#define T_   128
#define H_   128
#define G_   512
#define M_   32     // batch rows per CTA (MMA N)
#define NTHR 256    // 8 warps; warp w owns cells [w*16, w*16+16) x all 4 gates

// ---------------- device scratch ----------------
// Packed W image per layer: NC chunks of 64KB; chunk = [hi 32KB | lo 32KB];
// each half: 512 packed rows x 32 k bf16, ldmatrix-swizzled (seg ^= (p>>1)&3).
// Packed row p = (cell>>4)*64 + gate*16 + (cell&15)  => warp w m-tile m = gate m, cells w*16..+15.
__device__ __align__(1024) unsigned char g_wtA[3][8 * 65536];
__device__ float g_bias[3][G_];
__device__ float g_buf[(size_t)B_ * T_ * H_];   // fp32 activations, layers run in-place

// ---------------- helpers ----------------
__device__ __forceinline__ float tanha(float x) {
    float r; asm("tanh.approx.f32 %0, %1;" : "=f"(r) : "f"(x)); return r;
}
__device__ __forceinline__ float sigm(float x) { return 0.5f * tanha(0.5f * x) + 0.5f; }

union BU { __nv_bfloat162 h; uint32_t u; };
__device__ __forceinline__ uint32_t pack2(float a, float b) {
    BU v; v.h = __floats2bfloat162_rn(a, b); return v.u;
}
__device__ __forceinline__ float resid(float a) {
    return a - __bfloat162float(__float2bfloat16_rn(a));
}

#define HMMA(d, a, b) asm volatile( \
    "mma.sync.aligned.m16n8k16.row.col.f32.bf16.bf16.f32 " \
    "{%0,%1,%2,%3}, {%4,%5,%6,%7}, {%8,%9}, {%0,%1,%2,%3};" \
    : "+f"((d)[0]), "+f"((d)[1]), "+f"((d)[2]), "+f"((d)[3]) \
    : "r"((a)[0]), "r"((a)[1]), "r"((a)[2]), "r"((a)[3]), "r"((b)[0]), "r"((b)[1]))

#define LDSM4(r, addr) asm volatile( \
    "ldmatrix.sync.aligned.m8n8.x4.shared.b16 {%0,%1,%2,%3}, [%4];" \
    : "=r"((r)[0]), "=r"((r)[1]), "=r"((r)[2]), "=r"((r)[3]) : "r"(addr))

#define LDS32(r, addr) asm volatile("ld.shared.b32 %0, [%1];" : "=r"(r) : "r"(addr))

__device__ __forceinline__ void mbar_init(uint32_t a, uint32_t cnt) {
    asm volatile("mbarrier.init.shared.b64 [%0], %1;" :: "r"(a), "r"(cnt) : "memory");
}
__device__ __forceinline__ void mbar_expect(uint32_t a, uint32_t bytes) {
    asm volatile("mbarrier.arrive.expect_tx.shared::cta.b64 _, [%0], %1;"
                 :: "r"(a), "r"(bytes) : "memory");
}
__device__ __forceinline__ void mbar_wait(uint32_t a, uint32_t parity) {
    asm volatile(
        "{\n\t.reg .pred P;\n"
        "WL%=:\n\tmbarrier.try_wait.parity.shared::cta.b64 P, [%0], %1;\n"
        "\t@!P bra WL%=;\n\t}"
        :: "r"(a), "r"(parity) : "memory");
}
__device__ __forceinline__ void bulk_cp(uint32_t dst, const void* src, uint32_t bytes, uint32_t mbar) {
    asm volatile("cp.async.bulk.shared::cluster.global.mbarrier::complete_tx::bytes "
                 "[%0], [%1], %2, [%3];"
                 :: "r"(dst), "l"(src), "r"(bytes), "r"(mbar) : "memory");
}

// ---------------- prep: pack W (bf16 hi/lo) into ldmatrix-swizzled image + bias ----------------
__global__ void prep_w(const float* __restrict__ wih, const float* __restrict__ whh,
                       const float* __restrict__ bih, const float* __restrict__ bhh,
                       int layer, int IN, int INP) {
    int k = blockIdx.x;           // 0..K-1
    int row = threadIdx.x;        // 0..511 = gate*128 + cell
    float v;
    if (k < INP) v = (k < IN) ? wih[row * IN + k] : 0.f;
    else         v = whh[row * H_ + (k - INP)];
    __nv_bfloat16 hi = __float2bfloat16_rn(v);
    __nv_bfloat16 lo = __float2bfloat16_rn(v - __bfloat162float(hi));
    int gate = row >> 7, cell = row & 127;
    unsigned p = ((cell >> 4) << 6) + (gate << 4) + (cell & 15);
    int chunk = k >> 5;
    unsigned kb = (unsigned)(k & 31) * 2;
    unsigned off = p * 64 + ((((kb >> 4) ^ ((p >> 1) & 3)) << 4) | (kb & 15));
    *(__nv_bfloat16*)&g_wtA[layer][chunk * 65536 + off]         = hi;
    *(__nv_bfloat16*)&g_wtA[layer][chunk * 65536 + 32768 + off] = lo;
    if (k == 0) g_bias[layer][row] = bih[row] + bhh[row];
}

// ---------------- LSTM layer via mma.sync bf16 (3-term split), triple-buffered W ----------------
template <int IN, int INP, int NC>
__global__ void __launch_bounds__(NTHR, 1)
lstm_mma(const float* __restrict__ xext, int layer) {
    constexpr int K    = INP + H_;                          // 160 or 256
    constexpr int SROW = ((K * 2 + 127) / 128) * 128 + 16;  // bytes; ≡16 mod 128

    const float* x_in = (xext != nullptr) ? xext : g_buf;
    extern __shared__ unsigned char smem[];
    uint32_t sb = (uint32_t)__cvta_generic_to_shared(smem);
    uint32_t s0 = (sb + 1023) & ~1023u;
    uint32_t MB = s0;                         // three mbarriers (one per buffer)
    uint32_t A0 = s0 + 128;                   // 3 x 65536 W chunk buffers
    uint32_t U0 = A0 + 3 * 65536;             // u hi: 32 x SROW
    uint32_t U1 = U0 + 32 * SROW;             // u lo
    unsigned char* sp = smem + (s0 - sb);
    const unsigned UH = 128 + 3 * 65536;
    const unsigned UL = UH + 32 * SROW;

    const int tid = threadIdx.x, wid = tid >> 5, lane = tid & 31;
    const int g = lane >> 2, t4 = lane & 3;
    const int b0 = blockIdx.x * M_;
    const unsigned char* Wg = g_wtA[layer];

    // zero u (h0 = 0, pad region stays 0 forever)
    for (int i = tid; i < (64 * SROW) / 4; i += NTHR) ((uint32_t*)(sp + UH))[i] = 0;

    if (tid == 0) { mbar_init(MB, 1); mbar_init(MB + 8, 1); mbar_init(MB + 16, 1); }
    __syncthreads();
    if (tid == 0) {               // preload chunks 0,1 (prefetch depth 2)
        mbar_expect(MB, 65536);      bulk_cp(A0,         Wg,         65536, MB);
        mbar_expect(MB + 8, 65536);  bulk_cp(A0 + 65536, Wg + 65536, 65536, MB + 8);
    }

    const int cell0 = wid * 16 + g;
    float bias_v[4][2];
    #pragma unroll
    for (int m = 0; m < 4; m++) {
        bias_v[m][0] = g_bias[layer][m * 128 + cell0];
        bias_v[m][1] = g_bias[layer][m * 128 + cell0 + 8];
    }
    float acc[4][4][4];
    #pragma unroll
    for (int m = 0; m < 4; m++)
        #pragma unroll
        for (int nt = 0; nt < 4; nt++) {
            acc[m][nt][0] = acc[m][nt][1] = bias_v[m][0];
            acc[m][nt][2] = acc[m][nt][3] = bias_v[m][1];
        }
    float cst[16];
    #pragma unroll
    for (int i = 0; i < 16; i++) cst[i] = 0.f;

    int ph0 = 0, ph1 = 0, ph2 = 0;
    int gc = 0;                                  // global chunk counter
    const int TOT = T_ * NC;

    for (int t = 0; t < T_; t++) {
        // ---- stage x_t into u (bf16 hi/lo), rows = batch, cols = k ----
        constexpr int IN4 = IN / 4;
        for (int i = tid; i < M_ * IN4; i += NTHR) {
            int r  = i / IN4;
            int kv = i - r * IN4;
            float4 v = *(const float4*)&x_in[((size_t)(b0 + r) * T_ + t) * IN + kv * 4];
            unsigned off = (unsigned)r * SROW + kv * 8;
            *(uint32_t*)(sp + UH + off)     = pack2(v.x, v.y);
            *(uint32_t*)(sp + UH + off + 4) = pack2(v.z, v.w);
            *(uint32_t*)(sp + UL + off)     = pack2(resid(v.x), resid(v.y));
            *(uint32_t*)(sp + UL + off + 4) = pack2(resid(v.z), resid(v.w));
        }

        // ---- chunk loop ----
        for (int c = 0; c < NC; c++) {
            __syncthreads();  // staging done; buffer (gc+2)%3's previous chunk compute done
            int cur = gc % 3;
            if (tid == 0 && gc + 2 < TOT) {
                int tb = gc + 2 - (gc + 2) / 3 * 3;          // (gc+2)%3
                int cn = (c + 2 >= NC) ? (c + 2 - NC) : (c + 2);  // (gc+2)%NC
                mbar_expect(MB + tb * 8, 65536);
                bulk_cp(A0 + (unsigned)tb * 65536, Wg + (size_t)cn * 65536,
                        65536, MB + tb * 8);
            }
            if (cur == 0)      { mbar_wait(MB,      ph0); ph0 ^= 1; }
            else if (cur == 1) { mbar_wait(MB + 8,  ph1); ph1 ^= 1; }
            else               { mbar_wait(MB + 16, ph2); ph2 ^= 1; }

            uint32_t Ah = A0 + (unsigned)cur * 65536;
            uint32_t Al = Ah + 32768;
            #pragma unroll
            for (int ks = 0; ks < 2; ks++) {
                const int kb = c * 32 + ks * 16;
                uint32_t bh[4][2], bl[4][2];
                #pragma unroll
                for (int nt = 0; nt < 4; nt++) {
                    uint32_t uoff = (uint32_t)(nt * 8 + g) * SROW + (kb + 2 * t4) * 2;
                    LDS32(bh[nt][0], U0 + uoff); LDS32(bh[nt][1], U0 + uoff + 16);
                    LDS32(bl[nt][0], U1 + uoff); LDS32(bl[nt][1], U1 + uoff + 16);
                }
                unsigned p0  = (unsigned)wid * 64 + (lane & 15);
                unsigned seg = ((unsigned)(ks * 2 + (lane >> 4))) ^ ((p0 >> 1) & 3);
                uint32_t ab  = p0 * 64 + seg * 16;
                #pragma unroll
                for (int m = 0; m < 4; m++) {
                    uint32_t ah[4], al[4];
                    LDSM4(ah, Ah + ab + m * 1024);
                    LDSM4(al, Al + ab + m * 1024);
                    #pragma unroll
                    for (int nt = 0; nt < 4; nt++) {
                        HMMA(acc[m][nt], ah, bh[nt]);   // Whi*Uhi
                        HMMA(acc[m][nt], ah, bl[nt]);   // Whi*Ulo
                        HMMA(acc[m][nt], al, bh[nt]);   // Wlo*Uhi
                    }
                }
            }
            gc++;
        }
        __syncthreads();  // all MMA reads of u done before h writes

        // ---- epilogue: gates from registers, state update, h write-back ----
        #pragma unroll
        for (int ci = 0; ci < 2; ci++)
            #pragma unroll
            for (int nt = 0; nt < 4; nt++)
                #pragma unroll
                for (int par = 0; par < 2; par++) {
                    int e = ci * 2 + par;
                    float vi = acc[0][nt][e], vf = acc[1][nt][e];
                    float vg = acc[2][nt][e], vo = acc[3][nt][e];
                    int sidx = ci * 8 + nt * 2 + par;
                    float cn = sigm(vf) * cst[sidx] + sigm(vi) * tanha(vg);
                    cst[sidx] = cn;
                    float h = sigm(vo) * tanha(cn);
                    int cell = cell0 + ci * 8;
                    int b    = nt * 8 + t4 * 2 + par;
                    g_buf[((size_t)(b0 + b) * T_ + t) * H_ + cell] = h;
                    __nv_bfloat16 hh = __float2bfloat16_rn(h);
                    __nv_bfloat16 hl = __float2bfloat16_rn(h - __bfloat162float(hh));
                    unsigned ho = (unsigned)b * SROW + (INP + cell) * 2;
                    *(__nv_bfloat16*)(sp + UH + ho) = hh;
                    *(__nv_bfloat16*)(sp + UL + ho) = hl;
                }
        // reset accumulators to bias
        #pragma unroll
        for (int m = 0; m < 4; m++)
            #pragma unroll
            for (int nt = 0; nt < 4; nt++) {
                acc[m][nt][0] = acc[m][nt][1] = bias_v[m][0];
                acc[m][nt][2] = acc[m][nt][3] = bias_v[m][1];
            }
    }
}

// ---------------- FC head ----------------
__global__ void fc_kernel(const float* __restrict__ w1, const float* __restrict__ b1,
                          const float* __restrict__ w2, const float* __restrict__ b2,
                          float* __restrict__ out) {
    __shared__ float hsh[H_];
    __shared__ float red[4];
    int b = blockIdx.x;
    int tid = threadIdx.x;  // 128 threads

    hsh[tid] = g_buf[((size_t)b * T_ + (T_ - 1)) * H_ + tid];
    __syncthreads();

    float partial = 0.f;
    if (tid < 64) {
        float d = b1[tid];
        const float* wr = w1 + tid * H_;
        #pragma unroll 8
        for (int k = 0; k < H_; k++) d += wr[k] * hsh[k];
        partial = fmaxf(d, 0.f) * w2[tid];
    }
    #pragma unroll
    for (int off = 16; off > 0; off >>= 1)
        partial += __shfl_down_sync(0xffffffff, partial, off);
    if ((tid & 31) == 0) red[tid >> 5] = partial;
    __syncthreads();
    if (tid == 0) out[b] = red[0] + red[1] + b2[0];
}

// ---------------- launch ----------------
extern "C" void kernel_launch(void* const* d_in, const int* in_sizes, int n_in,
                              void* d_out, int out_size) {
    const float* x     = (const float*)d_in[0];
    const float* wih0  = (const float*)d_in[1];
    const float* whh0  = (const float*)d_in[2];
    const float* bih0  = (const float*)d_in[3];
    const float* bhh0  = (const float*)d_in[4];
    const float* wih1  = (const float*)d_in[5];
    const float* whh1  = (const float*)d_in[6];
    const float* bih1  = (const float*)d_in[7];
    const float* bhh1  = (const float*)d_in[8];
    const float* wih2  = (const float*)d_in[9];
    const float* whh2  = (const float*)d_in[10];
    const float* bih2  = (const float*)d_in[11];
    const float* bhh2  = (const float*)d_in[12];
    const float* fc1w  = (const float*)d_in[13];
    const float* fc1b  = (const float*)d_in[14];
    const float* fc2w  = (const float*)d_in[15];
    const float* fc2b  = (const float*)d_in[16];

    // dyn smem: 1024 align slack + 128 hdr + 3*65536 W + 64*SROW u
    const int SM5 = 1024 + 128 + 3 * 65536 + 64 * 400;  // K=160: 222,336
    const int SM8 = 1024 + 128 + 3 * 65536 + 64 * 528;  // K=256: 230,528
    cudaFuncSetAttribute(lstm_mma<8, 32, 5>,    cudaFuncAttributeMaxDynamicSharedMemorySize, SM5);
    cudaFuncSetAttribute(lstm_mma<128, 128, 8>, cudaFuncAttributeMaxDynamicSharedMemorySize, SM8);

    prep_w<<<160, 512>>>(wih0, whh0, bih0, bhh0, 0, 8,   32);
    prep_w<<<256, 512>>>(wih1, whh1, bih1, bhh1, 1, 128, 128);
    prep_w<<<256, 512>>>(wih2, whh2, bih2, bhh2, 2, 128, 128);

    lstm_mma<8, 32, 5>   <<<B_ / M_, NTHR, SM5>>>(x,       0);  // x   -> buf
    lstm_mma<128, 128, 8><<<B_ / M_, NTHR, SM8>>>(nullptr, 1);  // buf -> buf (in-place)
    lstm_mma<128, 128, 8><<<B_ / M_, NTHR, SM8>>>(nullptr, 2);  // buf -> buf (in-place)

    fc_kernel<<<B_, 128>>>(fc1w, fc1b, fc2w, fc2b, (float*)d_out);
}